// round 5
// baseline (speedup 1.0000x reference)
#include <cuda_runtime.h>
#include <cstdint>

#define T_STEPS 256
#define HH 512
#define WW 512
#define TILE 32
#define SMROWS 36           // tile + 2*2 halo rows
#define SMSTRIDE 40         // floats per staged row: cols [gx0-4, gx0+36)
#define NCHUNK 10           // float4 chunks per row
#define CHUNKS (SMROWS * NCHUNK)   // 360
#define STAGE_ELEMS (SMROWS * SMSTRIDE)

#define ALPHA_LIF 0.85f
#define V_TH      2.0f
#define ALPHA_LI  0.9f

typedef unsigned long long u64;

// ---- packed f32x2 helpers ----
__device__ __forceinline__ u64 pk(float lo, float hi) {
    u64 r; asm("mov.b64 %0, {%1, %2};" : "=l"(r) : "f"(lo), "f"(hi)); return r;
}
__device__ __forceinline__ void upk(u64 p, float& lo, float& hi) {
    asm("mov.b64 {%0, %1}, %2;" : "=f"(lo), "=f"(hi) : "l"(p));
}
__device__ __forceinline__ void ffma2(u64& acc, u64 a, u64 b) {
    asm("fma.rn.f32x2 %0, %1, %2, %0;" : "+l"(acc) : "l"(a), "l"(b));
}
__device__ __forceinline__ u64 ffma2g(u64 a, u64 b, u64 c) {
    u64 d; asm("fma.rn.f32x2 %0, %1, %2, %3;" : "=l"(d) : "l"(a), "l"(b), "l"(c)); return d;
}
__device__ __forceinline__ u64 fadd2(u64 a, u64 b) {
    u64 d; asm("add.rn.f32x2 %0, %1, %2;" : "=l"(d) : "l"(a), "l"(b)); return d;
}

// ---- cp.async helpers ----
__device__ __forceinline__ void cp_async16(float* smem_dst, const float* gsrc, bool pred) {
    uint32_t s = (uint32_t)__cvta_generic_to_shared(smem_dst);
    int srcsz = pred ? 16 : 0;
    asm volatile("cp.async.cg.shared.global [%0], [%1], 16, %2;\n"
                 :: "r"(s), "l"(gsrc), "r"(srcsz));
}
__device__ __forceinline__ void cp_async_commit() {
    asm volatile("cp.async.commit_group;\n" ::: "memory");
}
__device__ __forceinline__ void cp_async_wait1() {
    asm volatile("cp.async.wait_group 1;\n" ::: "memory");
}

__global__ __launch_bounds__(256, 2)
void snn_fused_kernel(const float* __restrict__ x,
                      const float* __restrict__ kw,
                      float* __restrict__ out) {
    __shared__ float sm[3][STAGE_ELEMS];

    const int tid = threadIdx.x;
    const int tx  = tid & 7;     // 0..7   -> 4 px each => 32 px wide
    const int ty  = tid >> 3;    // 0..31  -> 32 rows
    const int gx0 = blockIdx.x * TILE;
    const int gy0 = blockIdx.y * TILE;

    // conv weights -> packed (w,w) pairs
    u64 W2[25];
#pragma unroll
    for (int i = 0; i < 25; i++) { float wv = __ldg(&kw[i]); W2[i] = pk(wv, wv); }

    const u64 ALIF2 = pk(ALPHA_LIF, ALPHA_LIF);
    const u64 NTH2  = pk(-V_TH, -V_TH);
    const u64 ALI2  = pk(ALPHA_LI, ALPHA_LI);
    const u64 ZERO2 = pk(0.f, 0.f);

    // Vector staging map: 360 float4 chunks, <=2 per thread.
    // Chunk i: row r=i/10, chunk k=i%10 -> gcols [gx0-4+4k, +4), smem col 4k.
    int  goff[2];
    int  sdst[2];
    bool gok[2];
    bool act[2];
#pragma unroll
    for (int j = 0; j < 2; j++) {
        int i = tid + j * 256;
        act[j] = (i < CHUNKS);
        int r = i / NCHUNK;
        int k = i - r * NCHUNK;
        int gy  = gy0 - 2 + r;
        int gxc = gx0 - 4 + 4 * k;
        bool ok = act[j] && ((unsigned)gy < (unsigned)HH)
                         && (gxc >= 0) && (gxc <= WW - 4);
        gok[j]  = ok;
        goff[j] = ok ? (gy * WW + gxc) : 0;
        sdst[j] = r * SMSTRIDE + 4 * k;
    }

    // ---- prologue: stage t=0 and t=1 ----
#pragma unroll
    for (int j = 0; j < 2; j++)
        if (act[j]) cp_async16(&sm[0][sdst[j]], &x[goff[j]], gok[j]);
    cp_async_commit();
#pragma unroll
    for (int j = 0; j < 2; j++)
        if (act[j]) cp_async16(&sm[1][sdst[j]], &x[goff[j] + HH * WW], gok[j]);
    cp_async_commit();

    // packed per-pixel LIF / LI state
    u64 S1_01 = ZERO2, S1_23 = ZERO2, S2_01 = ZERO2, S2_23 = ZERO2;

    const int orow = (gy0 + ty) * WW + gx0 + tx * 4;
    float* ot = out + orow;
    const float* xfut = x + 2 * HH * WW;

    int cur = 0;

    for (int t = 0; t < T_STEPS; t++) {
        cp_async_wait1();
        __syncthreads();

        // stage t+2
        int nxt2 = cur + 2; if (nxt2 >= 3) nxt2 -= 3;
        if (t + 2 < T_STEPS) {
#pragma unroll
            for (int j = 0; j < 2; j++)
                if (act[j]) cp_async16(&sm[nxt2][sdst[j]], &xfut[goff[j]], gok[j]);
        }
        cp_async_commit();

        // 5x5 conv, 4 px, 4 independent packed chains (even/odd rows)
        u64 A01e = ZERO2, A23e = ZERO2, A01o = ZERO2, A23o = ZERO2;
#pragma unroll
        for (int r = 0; r < 5; r++) {
            // smem cols tx*4 .. tx*4+11; needed taps are cols +2..+9
            const float* rp = &sm[cur][(ty + r) * SMSTRIDE + tx * 4];
            float4 qa = *(const float4*)rp;        // q0..q3
            float4 qm = *(const float4*)(rp + 4);  // q4..q7
            float4 qb = *(const float4*)(rp + 8);  // q8..q11
            // f0..f7 = q2..q9
            u64 AP0 = pk(qa.z, qa.w);   // (f0,f1) reg-aligned pair
            u64 AP1 = pk(qm.x, qm.y);   // (f2,f3)
            u64 AP2 = pk(qm.z, qm.w);   // (f4,f5)
            u64 AP3 = pk(qb.x, qb.y);   // (f6,f7)
            u64 P12 = pk(qa.w, qm.x);   // (f1,f2)
            u64 P34 = pk(qm.y, qm.z);   // (f3,f4)
            u64 P56 = pk(qm.w, qb.x);   // (f5,f6)

            u64& A01 = (r & 1) ? A01o : A01e;
            u64& A23 = (r & 1) ? A23o : A23e;

            ffma2(A01, W2[r*5+0], AP0);
            ffma2(A01, W2[r*5+1], P12);
            ffma2(A01, W2[r*5+2], AP1);
            ffma2(A01, W2[r*5+3], P34);
            ffma2(A01, W2[r*5+4], AP2);

            ffma2(A23, W2[r*5+0], AP1);
            ffma2(A23, W2[r*5+1], P34);
            ffma2(A23, W2[r*5+2], AP2);
            ffma2(A23, W2[r*5+3], P56);
            ffma2(A23, W2[r*5+4], AP3);
        }
        u64 A01 = fadd2(A01e, A01o);
        u64 A23 = fadd2(A23e, A23o);

        // FastLIF (soft reset) + FastLI, packed
        u64 V01 = ffma2g(ALIF2, S1_01, A01);
        u64 V23 = ffma2g(ALIF2, S1_23, A23);

        float v0, v1, v2, v3;
        upk(V01, v0, v1);
        upk(V23, v2, v3);
        float k0 = (v0 >= V_TH) ? 1.0f : 0.0f;
        float k1 = (v1 >= V_TH) ? 1.0f : 0.0f;
        float k2 = (v2 >= V_TH) ? 1.0f : 0.0f;
        float k3 = (v3 >= V_TH) ? 1.0f : 0.0f;
        u64 K01 = pk(k0, k1);
        u64 K23 = pk(k2, k3);

        S1_01 = ffma2g(K01, NTH2, V01);     // v - k*Vth
        S1_23 = ffma2g(K23, NTH2, V23);
        S2_01 = ffma2g(ALI2, S2_01, K01);   // a_li*s2 + k
        S2_23 = ffma2g(ALI2, S2_23, K23);

        float4 o;
        upk(S2_01, o.x, o.y);
        upk(S2_23, o.z, o.w);
        *(float4*)ot = o;

        cur = cur + 1; if (cur >= 3) cur -= 3;
        xfut += HH * WW;
        ot   += HH * WW;
    }
}

extern "C" void kernel_launch(void* const* d_in, const int* in_sizes, int n_in,
                              void* d_out, int out_size) {
    const float* x  = (const float*)d_in[0];   // [256,1,512,512] f32
    const float* kw = (const float*)d_in[1];   // [1,1,5,5] f32
    float* out = (float*)d_out;                // [256,1,512,512] f32
    (void)in_sizes; (void)n_in; (void)out_size;

    dim3 grid(WW / TILE, HH / TILE);           // 16 x 16 tiles
    dim3 block(256);
    snn_fused_kernel<<<grid, block>>>(x, kw, out);
}

// round 7
// speedup vs baseline: 1.0574x; 1.0574x over previous
#include <cuda_runtime.h>
#include <cstdint>

#define T_STEPS 256
#define HH 512
#define WW 512
#define TILE 32
#define SMROWS 36           // tile + 2*2 halo rows
#define SMSTRIDE 40         // floats per staged row: cols [gx0-4, gx0+36)
#define NCHUNK 10           // float4 chunks per row
#define CHUNKS (SMROWS * NCHUNK)   // 360
#define STAGE_ELEMS (SMROWS * SMSTRIDE)

#define ALPHA_LIF 0.85f
#define V_TH      2.0f
#define ALPHA_LI  0.9f

typedef unsigned long long u64;

// ---- packed f32x2 helpers ----
__device__ __forceinline__ u64 pk(float lo, float hi) {
    u64 r; asm("mov.b64 %0, {%1, %2};" : "=l"(r) : "f"(lo), "f"(hi)); return r;
}
__device__ __forceinline__ void upk(u64 p, float& lo, float& hi) {
    asm("mov.b64 {%0, %1}, %2;" : "=f"(lo), "=f"(hi) : "l"(p));
}
__device__ __forceinline__ void ffma2(u64& acc, u64 a, u64 b) {
    asm("fma.rn.f32x2 %0, %1, %2, %0;" : "+l"(acc) : "l"(a), "l"(b));
}
__device__ __forceinline__ u64 ffma2g(u64 a, u64 b, u64 c) {
    u64 d; asm("fma.rn.f32x2 %0, %1, %2, %3;" : "=l"(d) : "l"(a), "l"(b), "l"(c)); return d;
}
__device__ __forceinline__ u64 fadd2(u64 a, u64 b) {
    u64 d; asm("add.rn.f32x2 %0, %1, %2;" : "=l"(d) : "l"(a), "l"(b)); return d;
}

// ---- cp.async helpers ----
__device__ __forceinline__ void cp_async16(float* smem_dst, const float* gsrc, bool pred) {
    uint32_t s = (uint32_t)__cvta_generic_to_shared(smem_dst);
    int srcsz = pred ? 16 : 0;
    asm volatile("cp.async.cg.shared.global [%0], [%1], 16, %2;\n"
                 :: "r"(s), "l"(gsrc), "r"(srcsz));
}
__device__ __forceinline__ void cp_async_commit() {
    asm volatile("cp.async.commit_group;\n" ::: "memory");
}
__device__ __forceinline__ void cp_async_wait1() {
    asm volatile("cp.async.wait_group 1;\n" ::: "memory");
}

__global__ __launch_bounds__(256, 2)
void snn_fused_kernel(const float* __restrict__ x,
                      const float* __restrict__ kw,
                      float* __restrict__ out) {
    __shared__ float sm[3][STAGE_ELEMS];

    const int tid = threadIdx.x;
    const int tx  = tid & 7;     // 0..7   -> 4 px each => 32 px wide
    const int ty  = tid >> 3;    // 0..31  -> 32 rows
    const int gx0 = blockIdx.x * TILE;
    const int gy0 = blockIdx.y * TILE;

    // conv weights -> packed (w,w) pairs
    u64 W2[25];
#pragma unroll
    for (int i = 0; i < 25; i++) { float wv = __ldg(&kw[i]); W2[i] = pk(wv, wv); }

    const u64 ALIF2 = pk(ALPHA_LIF, ALPHA_LIF);
    const u64 NTH2  = pk(-V_TH, -V_TH);
    const u64 ALI2  = pk(ALPHA_LI, ALPHA_LI);
    const u64 ZERO2 = pk(0.f, 0.f);

    // Vector staging map: 360 float4 chunks, <=2 per thread.
    // Chunk i: row r=i/10, chunk k=i%10 -> gcols [gx0-4+4k, +4), smem col 4k.
    int  goff[2];
    int  sdst[2];
    bool gok[2];
    bool act[2];
#pragma unroll
    for (int j = 0; j < 2; j++) {
        int i = tid + j * 256;
        act[j] = (i < CHUNKS);
        int r = i / NCHUNK;
        int k = i - r * NCHUNK;
        int gy  = gy0 - 2 + r;
        int gxc = gx0 - 4 + 4 * k;
        bool ok = act[j] && ((unsigned)gy < (unsigned)HH)
                         && (gxc >= 0) && (gxc <= WW - 4);
        gok[j]  = ok;
        goff[j] = ok ? (gy * WW + gxc) : 0;
        sdst[j] = r * SMSTRIDE + 4 * k;
    }

    // ---- prologue: stage t=0 and t=1 ----
#pragma unroll
    for (int j = 0; j < 2; j++)
        if (act[j]) cp_async16(&sm[0][sdst[j]], &x[goff[j]], gok[j]);
    cp_async_commit();
#pragma unroll
    for (int j = 0; j < 2; j++)
        if (act[j]) cp_async16(&sm[1][sdst[j]], &x[goff[j] + HH * WW], gok[j]);
    cp_async_commit();

    // packed per-pixel LIF / LI state
    u64 S1_01 = ZERO2, S1_23 = ZERO2, S2_01 = ZERO2, S2_23 = ZERO2;

    const int orow = (gy0 + ty) * WW + gx0 + tx * 4;
    float* ot = out + orow;
    const float* xfut = x + 2 * HH * WW;

    int cur = 0;

    for (int t = 0; t < T_STEPS; t++) {
        cp_async_wait1();
        __syncthreads();

        // stage t+2
        int nxt2 = cur + 2; if (nxt2 >= 3) nxt2 -= 3;
        if (t + 2 < T_STEPS) {
#pragma unroll
            for (int j = 0; j < 2; j++)
                if (act[j]) cp_async16(&sm[nxt2][sdst[j]], &xfut[goff[j]], gok[j]);
        }
        cp_async_commit();

        // 5x5 conv, 4 px, 4 independent packed chains (even/odd rows).
        // Taps for this thread are smem cols tx*4+2 .. tx*4+9:
        //   f0,f1 = rp+2,rp+3 ; f2..f5 = rp+4..rp+7 ; f6,f7 = rp+8,rp+9
        u64 A01e = ZERO2, A23e = ZERO2, A01o = ZERO2, A23o = ZERO2;
#pragma unroll
        for (int r = 0; r < 5; r++) {
            const float* rp = &sm[cur][(ty + r) * SMSTRIDE + tx * 4];
            float2 fa = *(const float2*)(rp + 2);   // f0,f1
            float4 qm = *(const float4*)(rp + 4);   // f2..f5
            float2 fb = *(const float2*)(rp + 8);   // f6,f7

            u64 AP0 = pk(fa.x, fa.y);   // (f0,f1)
            u64 AP1 = pk(qm.x, qm.y);   // (f2,f3)
            u64 AP2 = pk(qm.z, qm.w);   // (f4,f5)
            u64 AP3 = pk(fb.x, fb.y);   // (f6,f7)
            u64 P12 = pk(fa.y, qm.x);   // (f1,f2)
            u64 P34 = pk(qm.y, qm.z);   // (f3,f4)
            u64 P56 = pk(qm.w, fb.x);   // (f5,f6)

            u64& A01 = (r & 1) ? A01o : A01e;
            u64& A23 = (r & 1) ? A23o : A23e;

            ffma2(A01, W2[r*5+0], AP0);
            ffma2(A01, W2[r*5+1], P12);
            ffma2(A01, W2[r*5+2], AP1);
            ffma2(A01, W2[r*5+3], P34);
            ffma2(A01, W2[r*5+4], AP2);

            ffma2(A23, W2[r*5+0], AP1);
            ffma2(A23, W2[r*5+1], P34);
            ffma2(A23, W2[r*5+2], AP2);
            ffma2(A23, W2[r*5+3], P56);
            ffma2(A23, W2[r*5+4], AP3);
        }
        u64 A01 = fadd2(A01e, A01o);
        u64 A23 = fadd2(A23e, A23o);

        // FastLIF (soft reset) + FastLI, packed
        u64 V01 = ffma2g(ALIF2, S1_01, A01);
        u64 V23 = ffma2g(ALIF2, S1_23, A23);

        float v0, v1, v2, v3;
        upk(V01, v0, v1);
        upk(V23, v2, v3);
        float k0 = (v0 >= V_TH) ? 1.0f : 0.0f;
        float k1 = (v1 >= V_TH) ? 1.0f : 0.0f;
        float k2 = (v2 >= V_TH) ? 1.0f : 0.0f;
        float k3 = (v3 >= V_TH) ? 1.0f : 0.0f;
        u64 K01 = pk(k0, k1);
        u64 K23 = pk(k2, k3);

        S1_01 = ffma2g(K01, NTH2, V01);     // v - k*Vth
        S1_23 = ffma2g(K23, NTH2, V23);
        S2_01 = ffma2g(ALI2, S2_01, K01);   // a_li*s2 + k
        S2_23 = ffma2g(ALI2, S2_23, K23);

        float4 o;
        upk(S2_01, o.x, o.y);
        upk(S2_23, o.z, o.w);
        *(float4*)ot = o;

        cur = cur + 1; if (cur >= 3) cur -= 3;
        xfut += HH * WW;
        ot   += HH * WW;
    }
}

extern "C" void kernel_launch(void* const* d_in, const int* in_sizes, int n_in,
                              void* d_out, int out_size) {
    const float* x  = (const float*)d_in[0];   // [256,1,512,512] f32
    const float* kw = (const float*)d_in[1];   // [1,1,5,5] f32
    float* out = (float*)d_out;                // [256,1,512,512] f32
    (void)in_sizes; (void)n_in; (void)out_size;

    dim3 grid(WW / TILE, HH / TILE);           // 16 x 16 tiles
    dim3 block(256);
    snn_fused_kernel<<<grid, block>>>(x, kw, out);
}

// round 8
// speedup vs baseline: 1.2577x; 1.1894x over previous
#include <cuda_runtime.h>
#include <cstdint>

#define T_STEPS 256
#define HH 512
#define WW 512
#define TILE 32
#define SMROWS 36           // tile + 2*2 halo rows
#define SMSTRIDE 40         // floats per staged row: cols [gx0-4, gx0+36)
#define NCHUNK 10           // float4 chunks per row
#define CHUNKS (SMROWS * NCHUNK)   // 360
#define STAGE_ELEMS (SMROWS * SMSTRIDE)
#define NTHREADS 128

#define ALPHA_LIF 0.85f
#define V_TH      2.0f
#define ALPHA_LI  0.9f

typedef unsigned long long u64;

// ---- packed f32x2 helpers ----
__device__ __forceinline__ u64 pk(float lo, float hi) {
    u64 r; asm("mov.b64 %0, {%1, %2};" : "=l"(r) : "f"(lo), "f"(hi)); return r;
}
__device__ __forceinline__ void upk(u64 p, float& lo, float& hi) {
    asm("mov.b64 {%0, %1}, %2;" : "=f"(lo), "=f"(hi) : "l"(p));
}
__device__ __forceinline__ void ffma2(u64& acc, u64 a, u64 b) {
    asm("fma.rn.f32x2 %0, %1, %2, %0;" : "+l"(acc) : "l"(a), "l"(b));
}
__device__ __forceinline__ u64 ffma2g(u64 a, u64 b, u64 c) {
    u64 d; asm("fma.rn.f32x2 %0, %1, %2, %3;" : "=l"(d) : "l"(a), "l"(b), "l"(c)); return d;
}

// ---- cp.async helpers ----
__device__ __forceinline__ void cp_async16(float* smem_dst, const float* gsrc, bool pred) {
    uint32_t s = (uint32_t)__cvta_generic_to_shared(smem_dst);
    int srcsz = pred ? 16 : 0;
    asm volatile("cp.async.cg.shared.global [%0], [%1], 16, %2;\n"
                 :: "r"(s), "l"(gsrc), "r"(srcsz));
}
__device__ __forceinline__ void cp_async_commit() {
    asm volatile("cp.async.commit_group;\n" ::: "memory");
}
__device__ __forceinline__ void cp_async_wait1() {
    asm volatile("cp.async.wait_group 1;\n" ::: "memory");
}

__global__ __launch_bounds__(NTHREADS, 2)
void snn_fused_kernel(const float* __restrict__ x,
                      const float* __restrict__ kw,
                      float* __restrict__ out) {
    __shared__ float sm[3][STAGE_ELEMS];

    const int tid = threadIdx.x;
    const int tx  = tid & 7;      // 0..7  -> 4 px each => 32 px wide
    const int ty2 = tid >> 3;     // 0..15 -> 2 rows each => 32 rows
    const int yA  = ty2 * 2;      // first output row within tile
    const int gx0 = blockIdx.x * TILE;
    const int gy0 = blockIdx.y * TILE;

    // conv weights -> packed (w,w) pairs
    u64 W2[25];
#pragma unroll
    for (int i = 0; i < 25; i++) { float wv = __ldg(&kw[i]); W2[i] = pk(wv, wv); }

    const u64 ALIF2 = pk(ALPHA_LIF, ALPHA_LIF);
    const u64 NTH2  = pk(-V_TH, -V_TH);
    const u64 ALI2  = pk(ALPHA_LI, ALPHA_LI);
    const u64 ZERO2 = pk(0.f, 0.f);

    // Vector staging map: 360 float4 chunks, <=3 per thread (128 threads).
    int  goff[3];
    int  sdst[3];
    bool gok[3];
    bool act[3];
#pragma unroll
    for (int j = 0; j < 3; j++) {
        int i = tid + j * NTHREADS;
        act[j] = (i < CHUNKS);
        int r = i / NCHUNK;
        int k = i - r * NCHUNK;
        int gy  = gy0 - 2 + r;
        int gxc = gx0 - 4 + 4 * k;
        bool ok = act[j] && ((unsigned)gy < (unsigned)HH)
                         && (gxc >= 0) && (gxc <= WW - 4);
        gok[j]  = ok;
        goff[j] = ok ? (gy * WW + gxc) : 0;
        sdst[j] = r * SMSTRIDE + 4 * k;
    }

    // ---- prologue: stage t=0 and t=1 ----
#pragma unroll
    for (int j = 0; j < 3; j++)
        if (act[j]) cp_async16(&sm[0][sdst[j]], &x[goff[j]], gok[j]);
    cp_async_commit();
#pragma unroll
    for (int j = 0; j < 3; j++)
        if (act[j]) cp_async16(&sm[1][sdst[j]], &x[goff[j] + HH * WW], gok[j]);
    cp_async_commit();

    // packed per-pixel LIF / LI state for 2 rows x 4 cols
    u64 S1A0 = ZERO2, S1A1 = ZERO2, S1B0 = ZERO2, S1B1 = ZERO2;
    u64 S2A0 = ZERO2, S2A1 = ZERO2, S2B0 = ZERO2, S2B1 = ZERO2;

    const int orow = (gy0 + yA) * WW + gx0 + tx * 4;
    float* ot = out + orow;
    const float* xfut = x + 2 * HH * WW;

    int cur = 0;

    for (int t = 0; t < T_STEPS; t++) {
        cp_async_wait1();
        __syncthreads();

        // stage t+2
        int nxt2 = cur + 2; if (nxt2 >= 3) nxt2 -= 3;
        if (t + 2 < T_STEPS) {
#pragma unroll
            for (int j = 0; j < 3; j++)
                if (act[j]) cp_async16(&sm[nxt2][sdst[j]], &xfut[goff[j]], gok[j]);
        }
        cp_async_commit();

        // 5x5 conv for 2 output rows x 4 cols.
        // Loaded smem row (yA + r), r = 0..5. Taps f0..f7 = cols tx*4+2 .. tx*4+9.
        // All conv reads are conflict-free LDS.128 (quarter-warp has fixed row).
        u64 Aa0 = ZERO2, Aa1 = ZERO2;   // output row A, col-pairs (0,1) and (2,3)
        u64 Ab0 = ZERO2, Ab1 = ZERO2;   // output row B
#pragma unroll
        for (int r = 0; r < 6; r++) {
            const float* rp = &sm[cur][(yA + r) * SMSTRIDE + tx * 4];
            float4 qa = *(const float4*)rp;        // q0..q3
            float4 qm = *(const float4*)(rp + 4);  // q4..q7  (f2..f5)
            float4 qb = *(const float4*)(rp + 8);  // q8..q11 (f6..f9)

            u64 AP0 = pk(qa.z, qa.w);   // (f0,f1)
            u64 AP1 = pk(qm.x, qm.y);   // (f2,f3)
            u64 AP2 = pk(qm.z, qm.w);   // (f4,f5)
            u64 AP3 = pk(qb.x, qb.y);   // (f6,f7)
            u64 P12 = pk(qa.w, qm.x);   // (f1,f2)
            u64 P34 = pk(qm.y, qm.z);   // (f3,f4)
            u64 P56 = pk(qm.w, qb.x);   // (f5,f6)

            if (r < 5) {        // contributes to row A with weight row r
                ffma2(Aa0, W2[r*5+0], AP0);
                ffma2(Aa0, W2[r*5+1], P12);
                ffma2(Aa0, W2[r*5+2], AP1);
                ffma2(Aa0, W2[r*5+3], P34);
                ffma2(Aa0, W2[r*5+4], AP2);

                ffma2(Aa1, W2[r*5+0], AP1);
                ffma2(Aa1, W2[r*5+1], P34);
                ffma2(Aa1, W2[r*5+2], AP2);
                ffma2(Aa1, W2[r*5+3], P56);
                ffma2(Aa1, W2[r*5+4], AP3);
            }
            if (r >= 1) {       // contributes to row B with weight row r-1
                int q = (r - 1) * 5;
                ffma2(Ab0, W2[q+0], AP0);
                ffma2(Ab0, W2[q+1], P12);
                ffma2(Ab0, W2[q+2], AP1);
                ffma2(Ab0, W2[q+3], P34);
                ffma2(Ab0, W2[q+4], AP2);

                ffma2(Ab1, W2[q+0], AP1);
                ffma2(Ab1, W2[q+1], P34);
                ffma2(Ab1, W2[q+2], AP2);
                ffma2(Ab1, W2[q+3], P56);
                ffma2(Ab1, W2[q+4], AP3);
            }
        }

        // FastLIF (soft reset) + FastLI, packed — row A
        {
            u64 V0 = ffma2g(ALIF2, S1A0, Aa0);
            u64 V1 = ffma2g(ALIF2, S1A1, Aa1);
            float v0, v1, v2, v3;
            upk(V0, v0, v1);
            upk(V1, v2, v3);
            float k0 = (v0 >= V_TH) ? 1.0f : 0.0f;
            float k1 = (v1 >= V_TH) ? 1.0f : 0.0f;
            float k2 = (v2 >= V_TH) ? 1.0f : 0.0f;
            float k3 = (v3 >= V_TH) ? 1.0f : 0.0f;
            u64 K0 = pk(k0, k1);
            u64 K1 = pk(k2, k3);
            S1A0 = ffma2g(K0, NTH2, V0);
            S1A1 = ffma2g(K1, NTH2, V1);
            S2A0 = ffma2g(ALI2, S2A0, K0);
            S2A1 = ffma2g(ALI2, S2A1, K1);
            float4 o;
            upk(S2A0, o.x, o.y);
            upk(S2A1, o.z, o.w);
            *(float4*)ot = o;
        }
        // row B
        {
            u64 V0 = ffma2g(ALIF2, S1B0, Ab0);
            u64 V1 = ffma2g(ALIF2, S1B1, Ab1);
            float v0, v1, v2, v3;
            upk(V0, v0, v1);
            upk(V1, v2, v3);
            float k0 = (v0 >= V_TH) ? 1.0f : 0.0f;
            float k1 = (v1 >= V_TH) ? 1.0f : 0.0f;
            float k2 = (v2 >= V_TH) ? 1.0f : 0.0f;
            float k3 = (v3 >= V_TH) ? 1.0f : 0.0f;
            u64 K0 = pk(k0, k1);
            u64 K1 = pk(k2, k3);
            S1B0 = ffma2g(K0, NTH2, V0);
            S1B1 = ffma2g(K1, NTH2, V1);
            S2B0 = ffma2g(ALI2, S2B0, K0);
            S2B1 = ffma2g(ALI2, S2B1, K1);
            float4 o;
            upk(S2B0, o.x, o.y);
            upk(S2B1, o.z, o.w);
            *(float4*)(ot + WW) = o;
        }

        cur = cur + 1; if (cur >= 3) cur -= 3;
        xfut += HH * WW;
        ot   += HH * WW;
    }
}

extern "C" void kernel_launch(void* const* d_in, const int* in_sizes, int n_in,
                              void* d_out, int out_size) {
    const float* x  = (const float*)d_in[0];   // [256,1,512,512] f32
    const float* kw = (const float*)d_in[1];   // [1,1,5,5] f32
    float* out = (float*)d_out;                // [256,1,512,512] f32
    (void)in_sizes; (void)n_in; (void)out_size;

    dim3 grid(WW / TILE, HH / TILE);           // 16 x 16 tiles
    dim3 block(NTHREADS);
    snn_fused_kernel<<<grid, block>>>(x, kw, out);
}